// round 4
// baseline (speedup 1.0000x reference)
#include <cuda_runtime.h>
#include <cuda_bf16.h>

// Shapes:
//   xq      [1, 8, 128, 128]  f32
//   xk      [1, 1, 128, 128]  f32
//   rot_mat [1, 128, 128, 128] f32
// out[n,s,d] = sum_h x[n,s,h] * R[s,h,d];  out = concat(xq_out, xk_out)

#define SEQ_LEN   128
#define HEAD_DIM  128
#define N_HEADS   9
#define THREADS   256
#define N_PHASE   16            // h split into 16 phases of 8
#define D_PER_CTA 64            // d split across gridDim.y = 2
#define D4_PER_CTA (D_PER_CTA / 4)   // 16 float4 groups

__device__ __forceinline__ unsigned long long ffma2(unsigned long long a,
                                                    unsigned long long b,
                                                    unsigned long long c) {
    unsigned long long d;
    asm("fma.rn.f32x2 %0, %1, %2, %3;" : "=l"(d) : "l"(a), "l"(b), "l"(c));
    return d;
}

__device__ __forceinline__ unsigned long long pack2(float lo, float hi) {
    unsigned long long d;
    asm("mov.b64 %0, {%1, %2};" : "=l"(d) : "f"(lo), "f"(hi));
    return d;
}

__global__ __launch_bounds__(THREADS, 2)
void rotary_kernel(const float* __restrict__ xq,
                   const float* __restrict__ xk,
                   const float* __restrict__ R,
                   float* __restrict__ out)
{
    const int s   = blockIdx.x;           // sequence position
    const int dh  = blockIdx.y;           // which d-half (0 or 1)
    const int tid = threadIdx.x;
    const int d4l  = tid & (D4_PER_CTA - 1);   // 0..15: float4 column group within half
    const int hoff = tid >> 4;                 // 0..15: h phase

    // x values replicated {v,v} so the inner loop does LDS.64 feeding FFMA2
    __shared__ __align__(16) unsigned long long xs2[N_HEADS][HEAD_DIM];  // 9 KB
    __shared__ __align__(16) float partial[N_PHASE][N_HEADS][D_PER_CTA]; // 36 KB

    // ---- Stage x rows for this s (coalesced over h) ----
    for (int idx = tid; idx < N_HEADS * HEAD_DIM; idx += THREADS) {
        const int n = idx >> 7;
        const int h = idx & 127;
        float v;
        if (n < 8)
            v = xq[(size_t)n * (SEQ_LEN * HEAD_DIM) + (size_t)s * HEAD_DIM + h];
        else
            v = xk[(size_t)s * HEAD_DIM + h];
        const unsigned long long u = (unsigned long long)__float_as_uint(v);
        xs2[n][h] = (u << 32) | u;
    }
    __syncthreads();

    // ---- Front-batch 8 LDG.128 of R (MLP = 8), then compute ----
    const float4* __restrict__ R4 =
        reinterpret_cast<const float4*>(R + (size_t)s * HEAD_DIM * HEAD_DIM);
    const int col = dh * D4_PER_CTA + d4l;     // global float4 column group (0..31)

    float4 rv[8];
#pragma unroll
    for (int i = 0; i < 8; i++) {
        const int h = hoff + i * N_PHASE;
        rv[i] = R4[h * (HEAD_DIM / 4) + col];
    }

    unsigned long long acc0[N_HEADS], acc1[N_HEADS];
#pragma unroll
    for (int n = 0; n < N_HEADS; n++) { acc0[n] = 0ull; acc1[n] = 0ull; }

#pragma unroll
    for (int i = 0; i < 8; i++) {
        const int h = hoff + i * N_PHASE;
        const unsigned long long r01 = pack2(rv[i].x, rv[i].y);
        const unsigned long long r23 = pack2(rv[i].z, rv[i].w);
#pragma unroll
        for (int n = 0; n < N_HEADS; n++) {
            const unsigned long long xv = xs2[n][h];   // LDS.64 (broadcast per half-warp)
            acc0[n] = ffma2(xv, r01, acc0[n]);
            acc1[n] = ffma2(xv, r23, acc1[n]);
        }
    }

    // ---- Write phase partials ----
#pragma unroll
    for (int n = 0; n < N_HEADS; n++) {
        const float2 a0 = *reinterpret_cast<const float2*>(&acc0[n]);
        const float2 a1 = *reinterpret_cast<const float2*>(&acc1[n]);
        float4* p = reinterpret_cast<float4*>(&partial[hoff][n][d4l * 4]);
        *p = make_float4(a0.x, a0.y, a1.x, a1.y);
    }
    __syncthreads();

    // ---- Reduce 16 phases and store (coalesced over d) ----
    for (int idx = tid; idx < N_HEADS * D_PER_CTA; idx += THREADS) {
        const int n = idx / D_PER_CTA;
        const int d = idx % D_PER_CTA;
        float sum = 0.f;
#pragma unroll
        for (int p = 0; p < N_PHASE; p++)
            sum += partial[p][n][d];

        const int dglob = dh * D_PER_CTA + d;
        out[(size_t)n * (SEQ_LEN * HEAD_DIM) + (size_t)s * HEAD_DIM + dglob] = sum;
    }
}

extern "C" void kernel_launch(void* const* d_in, const int* in_sizes, int n_in,
                              void* d_out, int out_size)
{
    const float* xq = (const float*)d_in[0];
    const float* xk = (const float*)d_in[1];
    const float* R  = (const float*)d_in[2];
    float* out      = (float*)d_out;

    dim3 grid(SEQ_LEN, 2);
    rotary_kernel<<<grid, THREADS>>>(xq, xk, R, out);
}